// round 1
// baseline (speedup 1.0000x reference)
#include <cuda_runtime.h>
#include <cstdint>

// Problem shape (fixed by setup_inputs: B=4, S=2048, K=4096, N=4096)
namespace {
constexpr int M_DIM = 8192;
constexpr int N_DIM = 4096;
constexpr int K_DIM = 4096;
constexpr int K0C   = 256;
constexpr float TAU = 3.0f;
constexpr float EPS = 1e-6f;
}

// Scratch: per-element fail mask (1 = tail must be added). Written fully by
// head_kernel before tail_kernel reads it; no init required.
__device__ unsigned char g_mask[(long long)M_DIM * N_DIM];

// ---------------------------------------------------------------------------
// Head kernel: y1 = x0 @ w0^T, s2 = (x0^2) @ (w0^2)^T over k in [0, 256).
// Tile: BM=128, BN=64, BK=16. 256 threads, 8x4 per-thread microtile.
// Epilogue: gate, write out = passed ? bias : y1 + bias, write mask.
// ---------------------------------------------------------------------------
__global__ __launch_bounds__(256, 2)
void head_kernel(const float* __restrict__ X, const float* __restrict__ W,
                 const float* __restrict__ Bv, float* __restrict__ Out)
{
    __shared__ __align__(16) float As[16][132];  // [k][m], padded
    __shared__ __align__(16) float Bs[16][68];   // [k][n], padded

    const int bm  = blockIdx.y * 128;
    const int bn  = blockIdx.x * 64;
    const int tid = threadIdx.x;
    const int tx  = tid & 15;   // n direction (16 x 4 = 64)
    const int ty  = tid >> 4;   // m direction (16 x 8 = 128)

    float accY[8][4] = {};
    float accS[8][4] = {};

    for (int k0 = 0; k0 < K0C; k0 += 16) {
        // Load A tile: 128 rows x 16 k = 512 float4, 2 per thread
        #pragma unroll
        for (int l = 0; l < 2; ++l) {
            int idx = tid + l * 256;
            int row = idx >> 2;
            int kq  = idx & 3;
            float4 v = *reinterpret_cast<const float4*>(
                &X[(long long)(bm + row) * K_DIM + k0 + kq * 4]);
            As[kq * 4 + 0][row] = v.x;
            As[kq * 4 + 1][row] = v.y;
            As[kq * 4 + 2][row] = v.z;
            As[kq * 4 + 3][row] = v.w;
        }
        // Load B tile: 64 rows x 16 k = 256 float4, 1 per thread
        {
            int row = tid >> 2;
            int kq  = tid & 3;
            float4 v = *reinterpret_cast<const float4*>(
                &W[(long long)(bn + row) * K_DIM + k0 + kq * 4]);
            Bs[kq * 4 + 0][row] = v.x;
            Bs[kq * 4 + 1][row] = v.y;
            Bs[kq * 4 + 2][row] = v.z;
            Bs[kq * 4 + 3][row] = v.w;
        }
        __syncthreads();

        #pragma unroll
        for (int kk = 0; kk < 16; ++kk) {
            float a[8], b[4], aa[8], bb[4];
            const float4* ap = reinterpret_cast<const float4*>(&As[kk][ty * 8]);
            float4 a0 = ap[0], a1 = ap[1];
            a[0] = a0.x; a[1] = a0.y; a[2] = a0.z; a[3] = a0.w;
            a[4] = a1.x; a[5] = a1.y; a[6] = a1.z; a[7] = a1.w;
            const float4* bp = reinterpret_cast<const float4*>(&Bs[kk][tx * 4]);
            float4 b0 = bp[0];
            b[0] = b0.x; b[1] = b0.y; b[2] = b0.z; b[3] = b0.w;
            #pragma unroll
            for (int i = 0; i < 8; ++i) aa[i] = a[i] * a[i];
            #pragma unroll
            for (int j = 0; j < 4; ++j) bb[j] = b[j] * b[j];
            #pragma unroll
            for (int i = 0; i < 8; ++i)
                #pragma unroll
                for (int j = 0; j < 4; ++j) {
                    accY[i][j] = fmaf(a[i],  b[j],  accY[i][j]);
                    accS[i][j] = fmaf(aa[i], bb[j], accS[i][j]);
                }
        }
        __syncthreads();
    }

    // Epilogue: gate + write
    #pragma unroll
    for (int i = 0; i < 8; ++i) {
        const int m = bm + ty * 8 + i;
        #pragma unroll
        for (int j = 0; j < 4; ++j) {
            const int n = bn + tx * 4 + j;
            const float y1    = accY[i][j];
            const float denom = sqrtf(accS[i][j] * (1.0f / 256.0f) + EPS);
            const float t     = fabsf(y1) / fmaxf(denom, EPS);
            const bool passed = t < TAU;
            const long long o = (long long)m * N_DIM + n;
            Out[o]    = passed ? Bv[n] : (y1 + Bv[n]);
            g_mask[o] = passed ? 0 : 1;
        }
    }
}

// ---------------------------------------------------------------------------
// Tail kernel: acc = x[:,256:] @ w[:,256:]^T, added where mask == 1.
// Tile: BM=128, BN=128, BK=16. 256 threads, 8x8 per-thread microtile.
// ---------------------------------------------------------------------------
__global__ __launch_bounds__(256, 2)
void tail_kernel(const float* __restrict__ X, const float* __restrict__ W,
                 float* __restrict__ Out)
{
    __shared__ __align__(16) float As[16][132];
    __shared__ __align__(16) float Bs[16][132];

    const int bm  = blockIdx.y * 128;
    const int bn  = blockIdx.x * 128;
    const int tid = threadIdx.x;
    const int tx  = tid & 15;   // n direction (16 x 8 = 128)
    const int ty  = tid >> 4;   // m direction (16 x 8 = 128)

    float acc[8][8] = {};

    for (int k0 = K0C; k0 < K_DIM; k0 += 16) {
        #pragma unroll
        for (int l = 0; l < 2; ++l) {
            int idx = tid + l * 256;
            int row = idx >> 2;
            int kq  = idx & 3;
            float4 v = *reinterpret_cast<const float4*>(
                &X[(long long)(bm + row) * K_DIM + k0 + kq * 4]);
            As[kq * 4 + 0][row] = v.x;
            As[kq * 4 + 1][row] = v.y;
            As[kq * 4 + 2][row] = v.z;
            As[kq * 4 + 3][row] = v.w;
        }
        #pragma unroll
        for (int l = 0; l < 2; ++l) {
            int idx = tid + l * 256;
            int row = idx >> 2;
            int kq  = idx & 3;
            float4 v = *reinterpret_cast<const float4*>(
                &W[(long long)(bn + row) * K_DIM + k0 + kq * 4]);
            Bs[kq * 4 + 0][row] = v.x;
            Bs[kq * 4 + 1][row] = v.y;
            Bs[kq * 4 + 2][row] = v.z;
            Bs[kq * 4 + 3][row] = v.w;
        }
        __syncthreads();

        #pragma unroll
        for (int kk = 0; kk < 16; ++kk) {
            float a[8], b[8];
            const float4* ap = reinterpret_cast<const float4*>(&As[kk][ty * 8]);
            float4 a0 = ap[0], a1 = ap[1];
            a[0] = a0.x; a[1] = a0.y; a[2] = a0.z; a[3] = a0.w;
            a[4] = a1.x; a[5] = a1.y; a[6] = a1.z; a[7] = a1.w;
            const float4* bp = reinterpret_cast<const float4*>(&Bs[kk][tx * 8]);
            float4 b0 = bp[0], b1 = bp[1];
            b[0] = b0.x; b[1] = b0.y; b[2] = b0.z; b[3] = b0.w;
            b[4] = b1.x; b[5] = b1.y; b[6] = b1.z; b[7] = b1.w;
            #pragma unroll
            for (int i = 0; i < 8; ++i)
                #pragma unroll
                for (int j = 0; j < 8; ++j)
                    acc[i][j] = fmaf(a[i], b[j], acc[i][j]);
        }
        __syncthreads();
    }

    #pragma unroll
    for (int i = 0; i < 8; ++i) {
        const int m = bm + ty * 8 + i;
        #pragma unroll
        for (int j = 0; j < 8; ++j) {
            const int n = bn + tx * 8 + j;
            const long long o = (long long)m * N_DIM + n;
            if (g_mask[o]) Out[o] += acc[i][j];
        }
    }
}

// ---------------------------------------------------------------------------
extern "C" void kernel_launch(void* const* d_in, const int* in_sizes, int n_in,
                              void* d_out, int out_size)
{
    const float* x  = (const float*)d_in[0];   // [8192, 4096]
    const float* w  = (const float*)d_in[1];   // [4096, 4096]
    const float* bv = (const float*)d_in[2];   // [4096]
    float* out      = (float*)d_out;           // [8192, 4096]

    (void)in_sizes; (void)n_in; (void)out_size;

    dim3 headGrid(N_DIM / 64,  M_DIM / 128);   // 64 x 64
    dim3 tailGrid(N_DIM / 128, M_DIM / 128);   // 32 x 64

    head_kernel<<<headGrid, 256>>>(x, w, bv, out);
    tail_kernel<<<tailGrid, 256>>>(x, w, out);
}

// round 3
// speedup vs baseline: 2.0872x; 2.0872x over previous
#include <cuda_runtime.h>
#include <cuda_bf16.h>
#include <cstdint>

// ---------------------------------------------------------------------------
// Problem shape (fixed by setup_inputs: B=4, S=2048, K=4096, N=4096)
// ---------------------------------------------------------------------------
namespace {
constexpr int M_DIM = 8192;
constexpr int N_DIM = 4096;
constexpr int K_DIM = 4096;
constexpr int K0C   = 256;
constexpr int KT    = K_DIM - K0C;          // 3840 tail K
constexpr float TAU = 3.0f;
constexpr float EPS = 1e-6f;

// Tail HMMA tiling
constexpr int BM = 128;                      // M per CTA
constexpr int BN = 256;                      // N per CTA
constexpr int BK = 64;                       // bf16 K elems per chunk (128B rows)
constexpr int NCHUNK       = KT / BK;        // 60
constexpr int TOTAL_CHUNKS = 3 * NCHUNK;     // 180 (3 split passes)

constexpr int STAGE_A = BM * 128;            // 16384 B (128 rows x 128B)
constexpr int STAGE_B = BN * 128;            // 32768 B
constexpr int STAGE_BYTES = STAGE_A + STAGE_B;           // 49152
constexpr int SMEM_TOTAL_TAIL = 2 * STAGE_BYTES;         // 98304
}

// ---------------------------------------------------------------------------
// Device scratch (static; no dynamic allocation allowed)
// ---------------------------------------------------------------------------
__device__ __align__(1024) unsigned char  g_mask[(size_t)M_DIM * N_DIM];
__device__ __align__(1024) __nv_bfloat16  g_Xhi[(size_t)M_DIM * KT];
__device__ __align__(1024) __nv_bfloat16  g_Xlo[(size_t)M_DIM * KT];
__device__ __align__(1024) __nv_bfloat16  g_Whi[(size_t)N_DIM * KT];
__device__ __align__(1024) __nv_bfloat16  g_Wlo[(size_t)N_DIM * KT];

// ---------------------------------------------------------------------------
// Helpers (base-ISA only: cp.async / ldmatrix / mma.sync — no tcgen05)
// ---------------------------------------------------------------------------
__device__ __forceinline__ uint32_t smem_u32(const void* p) {
    uint32_t a;
    asm("{ .reg .u64 t; cvta.to.shared.u64 t, %1; cvt.u32.u64 %0, t; }" : "=r"(a) : "l"(p));
    return a;
}
#define SWZ128(off) ((off) ^ (((off) >> 3) & 0x70))

__device__ __forceinline__ void cp_async16(uint32_t dst, const void* src) {
    asm volatile("cp.async.cg.shared.global [%0], [%1], 16;"
                 :: "r"(dst), "l"(__cvta_generic_to_global(src)) : "memory");
}
#define CP_COMMIT() asm volatile("cp.async.commit_group;" ::: "memory")
#define CP_WAIT1()  asm volatile("cp.async.wait_group 1;" ::: "memory")

__device__ __forceinline__ void ldsm_x4(uint32_t& r0, uint32_t& r1, uint32_t& r2,
                                        uint32_t& r3, uint32_t addr) {
    asm volatile("ldmatrix.sync.aligned.m8n8.x4.shared.b16 {%0,%1,%2,%3}, [%4];"
                 : "=r"(r0), "=r"(r1), "=r"(r2), "=r"(r3) : "r"(addr));
}
__device__ __forceinline__ void mma_bf16(float* c, const uint32_t* a,
                                         uint32_t b0, uint32_t b1) {
    asm volatile("mma.sync.aligned.m16n8k16.row.col.f32.bf16.bf16.f32 "
                 "{%0,%1,%2,%3}, {%4,%5,%6,%7}, {%8,%9}, {%0,%1,%2,%3};"
                 : "+f"(c[0]), "+f"(c[1]), "+f"(c[2]), "+f"(c[3])
                 : "r"(a[0]), "r"(a[1]), "r"(a[2]), "r"(a[3]), "r"(b0), "r"(b1));
}

// ---------------------------------------------------------------------------
// Split conversion: fp32 tail cols [256,4096) -> bf16 hi + lo scratch
// ---------------------------------------------------------------------------
__global__ __launch_bounds__(256)
void split_convert(const float* __restrict__ src, __nv_bfloat16* __restrict__ hi,
                   __nv_bfloat16* __restrict__ lo, int nrows)
{
    const int per_row = KT / 4;
    int idx = blockIdx.x * 256 + threadIdx.x;
    if (idx >= nrows * per_row) return;
    int row = idx / per_row;
    int c   = (idx - row * per_row) * 4;
    float4 v = *reinterpret_cast<const float4*>(src + (size_t)row * K_DIM + K0C + c);
    float f[4] = {v.x, v.y, v.z, v.w};
    unsigned short hs[4], ls[4];
    #pragma unroll
    for (int i = 0; i < 4; ++i) {
        __nv_bfloat16 h = __float2bfloat16(f[i]);
        float r = f[i] - __bfloat162float(h);
        __nv_bfloat16 l = __float2bfloat16(r);
        hs[i] = __bfloat16_as_ushort(h);
        ls[i] = __bfloat16_as_ushort(l);
    }
    uint2 H, L;
    H.x = (uint32_t)hs[0] | ((uint32_t)hs[1] << 16);
    H.y = (uint32_t)hs[2] | ((uint32_t)hs[3] << 16);
    L.x = (uint32_t)ls[0] | ((uint32_t)ls[1] << 16);
    L.y = (uint32_t)ls[2] | ((uint32_t)ls[3] << 16);
    *reinterpret_cast<uint2*>(hi + (size_t)row * KT + c) = H;
    *reinterpret_cast<uint2*>(lo + (size_t)row * KT + c) = L;
}

// ---------------------------------------------------------------------------
// Head kernel (fp32 SIMT decision path — unchanged, proven rel_err 1.1e-6)
// ---------------------------------------------------------------------------
__global__ __launch_bounds__(256, 2)
void head_kernel(const float* __restrict__ X, const float* __restrict__ W,
                 const float* __restrict__ Bv, float* __restrict__ Out)
{
    __shared__ __align__(16) float As[16][132];
    __shared__ __align__(16) float Bs[16][68];

    const int bm  = blockIdx.y * 128;
    const int bn  = blockIdx.x * 64;
    const int tid = threadIdx.x;
    const int tx  = tid & 15;
    const int ty  = tid >> 4;

    float accY[8][4] = {};
    float accS[8][4] = {};

    for (int k0 = 0; k0 < K0C; k0 += 16) {
        #pragma unroll
        for (int l = 0; l < 2; ++l) {
            int idx = tid + l * 256;
            int row = idx >> 2;
            int kq  = idx & 3;
            float4 v = *reinterpret_cast<const float4*>(
                &X[(size_t)(bm + row) * K_DIM + k0 + kq * 4]);
            As[kq * 4 + 0][row] = v.x; As[kq * 4 + 1][row] = v.y;
            As[kq * 4 + 2][row] = v.z; As[kq * 4 + 3][row] = v.w;
        }
        {
            int row = tid >> 2;
            int kq  = tid & 3;
            float4 v = *reinterpret_cast<const float4*>(
                &W[(size_t)(bn + row) * K_DIM + k0 + kq * 4]);
            Bs[kq * 4 + 0][row] = v.x; Bs[kq * 4 + 1][row] = v.y;
            Bs[kq * 4 + 2][row] = v.z; Bs[kq * 4 + 3][row] = v.w;
        }
        __syncthreads();

        #pragma unroll
        for (int kk = 0; kk < 16; ++kk) {
            float a[8], b[4], aa[8], bb[4];
            const float4* ap = reinterpret_cast<const float4*>(&As[kk][ty * 8]);
            float4 a0 = ap[0], a1 = ap[1];
            a[0]=a0.x; a[1]=a0.y; a[2]=a0.z; a[3]=a0.w;
            a[4]=a1.x; a[5]=a1.y; a[6]=a1.z; a[7]=a1.w;
            const float4* bp = reinterpret_cast<const float4*>(&Bs[kk][tx * 4]);
            float4 b0 = bp[0];
            b[0]=b0.x; b[1]=b0.y; b[2]=b0.z; b[3]=b0.w;
            #pragma unroll
            for (int i = 0; i < 8; ++i) aa[i] = a[i] * a[i];
            #pragma unroll
            for (int j = 0; j < 4; ++j) bb[j] = b[j] * b[j];
            #pragma unroll
            for (int i = 0; i < 8; ++i)
                #pragma unroll
                for (int j = 0; j < 4; ++j) {
                    accY[i][j] = fmaf(a[i],  b[j],  accY[i][j]);
                    accS[i][j] = fmaf(aa[i], bb[j], accS[i][j]);
                }
        }
        __syncthreads();
    }

    #pragma unroll
    for (int i = 0; i < 8; ++i) {
        const int m = bm + ty * 8 + i;
        #pragma unroll
        for (int j = 0; j < 4; ++j) {
            const int n = bn + tx * 4 + j;
            const float y1    = accY[i][j];
            const float denom = sqrtf(accS[i][j] * (1.0f / 256.0f) + EPS);
            const float t     = fabsf(y1) / fmaxf(denom, EPS);
            const bool passed = t < TAU;
            const size_t o = (size_t)m * N_DIM + n;
            Out[o]    = passed ? Bv[n] : (y1 + Bv[n]);
            g_mask[o] = passed ? 0 : 1;
        }
    }
}

// ---------------------------------------------------------------------------
// Tail kernel: bf16 2-split GEMM on HMMA (mma.sync), 3 accumulating passes.
// CTA 128x256, 8 warps (2m x 4n), warp tile 64x64, BK=64, cp.async 2-stage.
// ---------------------------------------------------------------------------
__global__ __launch_bounds__(256, 1)
void tail_mma_kernel(float* __restrict__ Out)
{
    extern __shared__ __align__(1024) char smem[];
    const uint32_t sbase = smem_u32(smem);
    const int tid  = threadIdx.x;
    const int wid  = tid >> 5;
    const int lane = tid & 31;

    const int bm = blockIdx.y * BM;
    const int bn = blockIdx.x * BN;

    const int warpM = (wid >> 2) * 64;   // 0 or 64
    const int warpN = (wid & 3) * 64;    // 0,64,128,192

    // ldmatrix per-thread row/k-offset decomposition
    const int sub = lane >> 3;           // 0..3
    const int tr  = lane & 7;
    const int aRow = (sub & 1) * 8 + tr;   // within 16-row tile
    const int aK8  = (sub >> 1);           // 0/1 (8-elem k half)
    const int bRow = (sub >> 1) * 8 + tr;  // within 16-row (n) pair
    const int bK8  = (sub & 1);

    const __nv_bfloat16* Aseg[3] = {g_Xhi, g_Xhi, g_Xlo};
    const __nv_bfloat16* Bseg[3] = {g_Whi, g_Wlo, g_Whi};

    float acc[4][8][4];
    #pragma unroll
    for (int i = 0; i < 4; ++i)
        #pragma unroll
        for (int j = 0; j < 8; ++j)
            #pragma unroll
            for (int q = 0; q < 4; ++q) acc[i][j][q] = 0.0f;

    // ---- stage loader ----
    auto load_chunk = [&](int it, int buf) {
        const int seg = it / NCHUNK;
        const int kk  = (it - seg * NCHUNK) * BK;
        const __nv_bfloat16* Ap = Aseg[seg] + (size_t)bm * KT + kk;
        const __nv_bfloat16* Bp = Bseg[seg] + (size_t)bn * KT + kk;
        const uint32_t aOff = buf * STAGE_BYTES;
        const uint32_t bOff = aOff + STAGE_A;
        #pragma unroll
        for (int l = 0; l < 4; ++l) {
            int idx = tid + l * 256;
            int r = idx >> 3, c = idx & 7;
            cp_async16(sbase + aOff + SWZ128((uint32_t)(r * 128 + c * 16)),
                       Ap + (size_t)r * KT + c * 8);
        }
        #pragma unroll
        for (int l = 0; l < 8; ++l) {
            int idx = tid + l * 256;
            int r = idx >> 3, c = idx & 7;
            cp_async16(sbase + bOff + SWZ128((uint32_t)(r * 128 + c * 16)),
                       Bp + (size_t)r * KT + c * 8);
        }
    };

    load_chunk(0, 0);
    CP_COMMIT();

    for (int it = 0; it < TOTAL_CHUNKS; ++it) {
        const int buf = it & 1;
        if (it + 1 < TOTAL_CHUNKS) load_chunk(it + 1, buf ^ 1);
        CP_COMMIT();
        CP_WAIT1();
        __syncthreads();

        const uint32_t aBase = sbase + buf * STAGE_BYTES;
        const uint32_t bBase = aBase + STAGE_A;

        #pragma unroll
        for (int ks = 0; ks < 4; ++ks) {
            uint32_t afrag[4][4];
            #pragma unroll
            for (int mi = 0; mi < 4; ++mi) {
                int row = warpM + mi * 16 + aRow;
                uint32_t byte = (uint32_t)(row * 128) +
                                ((uint32_t)((ks * 2 + aK8) * 16) ^ ((row & 7) * 16));
                ldsm_x4(afrag[mi][0], afrag[mi][1], afrag[mi][2], afrag[mi][3],
                        aBase + byte);
            }
            #pragma unroll
            for (int pr = 0; pr < 4; ++pr) {      // n8-tile pairs
                int row = warpN + pr * 16 + bRow;
                uint32_t byte = (uint32_t)(row * 128) +
                                ((uint32_t)((ks * 2 + bK8) * 16) ^ ((row & 7) * 16));
                uint32_t b0, b1, b2, b3;
                ldsm_x4(b0, b1, b2, b3, bBase + byte);
                #pragma unroll
                for (int mi = 0; mi < 4; ++mi) {
                    mma_bf16(acc[mi][pr * 2 + 0], afrag[mi], b0, b1);
                    mma_bf16(acc[mi][pr * 2 + 1], afrag[mi], b2, b3);
                }
            }
        }
        __syncthreads();
    }

    // ---- masked RMW epilogue straight from accumulators ----
    const int mrow = lane >> 2;          // 0..7
    const int ncol = (lane & 3) * 2;
    #pragma unroll
    for (int mi = 0; mi < 4; ++mi) {
        #pragma unroll
        for (int ni = 0; ni < 8; ++ni) {
            const int m = bm + warpM + mi * 16 + mrow;
            const int n = bn + warpN + ni * 8 + ncol;
            size_t o = (size_t)m * N_DIM + n;
            if (g_mask[o])     Out[o]     += acc[mi][ni][0];
            if (g_mask[o + 1]) Out[o + 1] += acc[mi][ni][1];
            size_t o2 = o + (size_t)8 * N_DIM;
            if (g_mask[o2])     Out[o2]     += acc[mi][ni][2];
            if (g_mask[o2 + 1]) Out[o2 + 1] += acc[mi][ni][3];
        }
    }
}

// ---------------------------------------------------------------------------
extern "C" void kernel_launch(void* const* d_in, const int* in_sizes, int n_in,
                              void* d_out, int out_size)
{
    const float* x  = (const float*)d_in[0];   // [8192, 4096]
    const float* w  = (const float*)d_in[1];   // [4096, 4096]
    const float* bv = (const float*)d_in[2];   // [4096]
    float* out      = (float*)d_out;           // [8192, 4096]
    (void)in_sizes; (void)n_in; (void)out_size;

    cudaFuncSetAttribute(tail_mma_kernel,
                         cudaFuncAttributeMaxDynamicSharedMemorySize, SMEM_TOTAL_TAIL);

    __nv_bfloat16 *xhi, *xlo, *whi, *wlo;
    cudaGetSymbolAddress((void**)&xhi, g_Xhi);
    cudaGetSymbolAddress((void**)&xlo, g_Xlo);
    cudaGetSymbolAddress((void**)&whi, g_Whi);
    cudaGetSymbolAddress((void**)&wlo, g_Wlo);

    // Conversions (independent of head)
    split_convert<<<(M_DIM * (KT / 4) + 255) / 256, 256>>>(x, xhi, xlo, M_DIM);
    split_convert<<<(N_DIM * (KT / 4) + 255) / 256, 256>>>(w, whi, wlo, N_DIM);

    // Decision path (fp32 exact)
    dim3 headGrid(N_DIM / 64, M_DIM / 128);
    head_kernel<<<headGrid, 256>>>(x, w, bv, out);

    // Tail value path (bf16 2-split on HMMA)
    dim3 tailGrid(N_DIM / BN, M_DIM / BM);   // (16, 64)
    tail_mma_kernel<<<tailGrid, 256, SMEM_TOTAL_TAIL>>>(out);
}

// round 4
// speedup vs baseline: 4.2139x; 2.0189x over previous
#include <cuda_runtime.h>
#include <cuda_fp16.h>
#include <cstdint>

// ---------------------------------------------------------------------------
// Problem shape (fixed by setup_inputs: B=4, S=2048, K=4096, N=4096)
// ---------------------------------------------------------------------------
namespace {
constexpr int M_DIM = 8192;
constexpr int N_DIM = 4096;
constexpr int K_DIM = 4096;
constexpr int K0C   = 256;
constexpr int KT    = K_DIM - K0C;          // 3840 tail K
constexpr float TAU = 3.0f;
constexpr float EPS = 1e-6f;

// Tail HMMA tiling (single-pass fp16)
constexpr int BM = 128;
constexpr int BN = 128;
constexpr int BK = 64;                       // fp16 K elems per chunk (128B rows)
constexpr int NCHUNK = KT / BK;              // 60

constexpr int STAGE_A = BM * 128;            // 16384 B
constexpr int STAGE_B = BN * 128;            // 16384 B
constexpr int STAGE_BYTES = STAGE_A + STAGE_B;   // 32768
constexpr int NSTAGE = 3;
constexpr int SMEM_TOTAL_TAIL = NSTAGE * STAGE_BYTES;  // 98304
}

// ---------------------------------------------------------------------------
// Device scratch (static; no dynamic allocation allowed)
// ---------------------------------------------------------------------------
__device__ __align__(1024) unsigned char g_mask[(size_t)M_DIM * N_DIM];
__device__ __align__(1024) __half        g_Xh[(size_t)M_DIM * KT];
__device__ __align__(1024) __half        g_Wh[(size_t)N_DIM * KT];

// ---------------------------------------------------------------------------
// Helpers (base-ISA only: cp.async / ldmatrix / mma.sync)
// ---------------------------------------------------------------------------
__device__ __forceinline__ uint32_t smem_u32(const void* p) {
    uint32_t a;
    asm("{ .reg .u64 t; cvta.to.shared.u64 t, %1; cvt.u32.u64 %0, t; }" : "=r"(a) : "l"(p));
    return a;
}
#define SWZ128(off) ((off) ^ (((off) >> 3) & 0x70))

__device__ __forceinline__ void cp_async16(uint32_t dst, const void* src) {
    asm volatile("cp.async.cg.shared.global [%0], [%1], 16;"
                 :: "r"(dst), "l"(__cvta_generic_to_global(src)) : "memory");
}
#define CP_COMMIT() asm volatile("cp.async.commit_group;" ::: "memory")
#define CP_WAIT2()  asm volatile("cp.async.wait_group 2;" ::: "memory")

__device__ __forceinline__ void ldsm_x4(uint32_t& r0, uint32_t& r1, uint32_t& r2,
                                        uint32_t& r3, uint32_t addr) {
    asm volatile("ldmatrix.sync.aligned.m8n8.x4.shared.b16 {%0,%1,%2,%3}, [%4];"
                 : "=r"(r0), "=r"(r1), "=r"(r2), "=r"(r3) : "r"(addr));
}
__device__ __forceinline__ void mma_fp16(float* c, const uint32_t* a,
                                         uint32_t b0, uint32_t b1) {
    asm volatile("mma.sync.aligned.m16n8k16.row.col.f32.f16.f16.f32 "
                 "{%0,%1,%2,%3}, {%4,%5,%6,%7}, {%8,%9}, {%0,%1,%2,%3};"
                 : "+f"(c[0]), "+f"(c[1]), "+f"(c[2]), "+f"(c[3])
                 : "r"(a[0]), "r"(a[1]), "r"(a[2]), "r"(a[3]), "r"(b0), "r"(b1));
}

// ---------------------------------------------------------------------------
// Convert: fp32 tail cols [256,4096) -> fp16 scratch (RN)
// ---------------------------------------------------------------------------
__global__ __launch_bounds__(256)
void conv_half(const float* __restrict__ src, __half* __restrict__ dst, int nrows)
{
    const int per_row = KT / 4;
    int idx = blockIdx.x * 256 + threadIdx.x;
    if (idx >= nrows * per_row) return;
    int row = idx / per_row;
    int c   = (idx - row * per_row) * 4;
    float4 v = *reinterpret_cast<const float4*>(src + (size_t)row * K_DIM + K0C + c);
    __half2 h0 = __floats2half2_rn(v.x, v.y);
    __half2 h1 = __floats2half2_rn(v.z, v.w);
    uint2 out;
    out.x = *reinterpret_cast<uint32_t*>(&h0);
    out.y = *reinterpret_cast<uint32_t*>(&h1);
    *reinterpret_cast<uint2*>(dst + (size_t)row * KT + c) = out;
}

// ---------------------------------------------------------------------------
// Head kernel (fp32 SIMT decision path — unchanged, proven rel_err 1.1e-6)
// ---------------------------------------------------------------------------
__global__ __launch_bounds__(256, 2)
void head_kernel(const float* __restrict__ X, const float* __restrict__ W,
                 const float* __restrict__ Bv, float* __restrict__ Out)
{
    __shared__ __align__(16) float As[16][132];
    __shared__ __align__(16) float Bs[16][68];

    const int bm  = blockIdx.y * 128;
    const int bn  = blockIdx.x * 64;
    const int tid = threadIdx.x;
    const int tx  = tid & 15;
    const int ty  = tid >> 4;

    float accY[8][4] = {};
    float accS[8][4] = {};

    for (int k0 = 0; k0 < K0C; k0 += 16) {
        #pragma unroll
        for (int l = 0; l < 2; ++l) {
            int idx = tid + l * 256;
            int row = idx >> 2;
            int kq  = idx & 3;
            float4 v = *reinterpret_cast<const float4*>(
                &X[(size_t)(bm + row) * K_DIM + k0 + kq * 4]);
            As[kq * 4 + 0][row] = v.x; As[kq * 4 + 1][row] = v.y;
            As[kq * 4 + 2][row] = v.z; As[kq * 4 + 3][row] = v.w;
        }
        {
            int row = tid >> 2;
            int kq  = tid & 3;
            float4 v = *reinterpret_cast<const float4*>(
                &W[(size_t)(bn + row) * K_DIM + k0 + kq * 4]);
            Bs[kq * 4 + 0][row] = v.x; Bs[kq * 4 + 1][row] = v.y;
            Bs[kq * 4 + 2][row] = v.z; Bs[kq * 4 + 3][row] = v.w;
        }
        __syncthreads();

        #pragma unroll
        for (int kk = 0; kk < 16; ++kk) {
            float a[8], b[4], aa[8], bb[4];
            const float4* ap = reinterpret_cast<const float4*>(&As[kk][ty * 8]);
            float4 a0 = ap[0], a1 = ap[1];
            a[0]=a0.x; a[1]=a0.y; a[2]=a0.z; a[3]=a0.w;
            a[4]=a1.x; a[5]=a1.y; a[6]=a1.z; a[7]=a1.w;
            const float4* bp = reinterpret_cast<const float4*>(&Bs[kk][tx * 4]);
            float4 b0 = bp[0];
            b[0]=b0.x; b[1]=b0.y; b[2]=b0.z; b[3]=b0.w;
            #pragma unroll
            for (int i = 0; i < 8; ++i) aa[i] = a[i] * a[i];
            #pragma unroll
            for (int j = 0; j < 4; ++j) bb[j] = b[j] * b[j];
            #pragma unroll
            for (int i = 0; i < 8; ++i)
                #pragma unroll
                for (int j = 0; j < 4; ++j) {
                    accY[i][j] = fmaf(a[i],  b[j],  accY[i][j]);
                    accS[i][j] = fmaf(aa[i], bb[j], accS[i][j]);
                }
        }
        __syncthreads();
    }

    #pragma unroll
    for (int i = 0; i < 8; ++i) {
        const int m = bm + ty * 8 + i;
        #pragma unroll
        for (int j = 0; j < 4; ++j) {
            const int n = bn + tx * 4 + j;
            const float y1    = accY[i][j];
            const float denom = sqrtf(accS[i][j] * (1.0f / 256.0f) + EPS);
            const float t     = fabsf(y1) / fmaxf(denom, EPS);
            const bool passed = t < TAU;
            const size_t o = (size_t)m * N_DIM + n;
            Out[o]    = passed ? Bv[n] : (y1 + Bv[n]);
            g_mask[o] = passed ? 0 : 1;
        }
    }
}

// ---------------------------------------------------------------------------
// Tail kernel: single-pass fp16 GEMM on HMMA.
// CTA 128x128, 8 warps (4m x 2n), warp tile 32x64, BK=64, 3-stage cp.async.
// 2 CTAs/SM (96KB smem, <=128 regs).
// ---------------------------------------------------------------------------
__global__ __launch_bounds__(256, 2)
void tail_mma_kernel(float* __restrict__ Out)
{
    extern __shared__ __align__(1024) char smem[];
    const uint32_t sbase = smem_u32(smem);
    const int tid  = threadIdx.x;
    const int wid  = tid >> 5;
    const int lane = tid & 31;

    const int bm = blockIdx.y * BM;
    const int bn = blockIdx.x * BN;

    const int warpM = (wid & 3) * 32;    // 0,32,64,96
    const int warpN = (wid >> 2) * 64;   // 0,64

    // ldmatrix per-thread decomposition (proven in R3)
    const int sub = lane >> 3;
    const int tr  = lane & 7;
    const int aRow = (sub & 1) * 8 + tr;
    const int aK8  = (sub >> 1);
    const int bRow = (sub >> 1) * 8 + tr;
    const int bK8  = (sub & 1);

    float acc[2][8][4];
    #pragma unroll
    for (int i = 0; i < 2; ++i)
        #pragma unroll
        for (int j = 0; j < 8; ++j)
            #pragma unroll
            for (int q = 0; q < 4; ++q) acc[i][j][q] = 0.0f;

    auto load_chunk = [&](int it, int buf) {
        const __half* Ap = g_Xh + (size_t)bm * KT + it * BK;
        const __half* Bp = g_Wh + (size_t)bn * KT + it * BK;
        const uint32_t aOff = buf * STAGE_BYTES;
        const uint32_t bOff = aOff + STAGE_A;
        #pragma unroll
        for (int l = 0; l < 4; ++l) {
            int idx = tid + l * 256;
            int r = idx >> 3, c = idx & 7;
            cp_async16(sbase + aOff + SWZ128((uint32_t)(r * 128 + c * 16)),
                       Ap + (size_t)r * KT + c * 8);
        }
        #pragma unroll
        for (int l = 0; l < 4; ++l) {
            int idx = tid + l * 256;
            int r = idx >> 3, c = idx & 7;
            cp_async16(sbase + bOff + SWZ128((uint32_t)(r * 128 + c * 16)),
                       Bp + (size_t)r * KT + c * 8);
        }
    };

    load_chunk(0, 0); CP_COMMIT();
    load_chunk(1, 1); CP_COMMIT();

    int buf = 0;
    for (int it = 0; it < NCHUNK; ++it) {
        if (it + 2 < NCHUNK) {
            int nb = buf + 2; if (nb >= NSTAGE) nb -= NSTAGE;
            load_chunk(it + 2, nb);
        }
        CP_COMMIT();
        CP_WAIT2();
        __syncthreads();

        const uint32_t aBase = sbase + buf * STAGE_BYTES;
        const uint32_t bBase = aBase + STAGE_A;

        #pragma unroll
        for (int ks = 0; ks < 4; ++ks) {
            uint32_t afrag[2][4];
            #pragma unroll
            for (int mi = 0; mi < 2; ++mi) {
                int row = warpM + mi * 16 + aRow;
                uint32_t byte = (uint32_t)(row * 128) +
                                ((uint32_t)((ks * 2 + aK8) * 16) ^ ((row & 7) * 16));
                ldsm_x4(afrag[mi][0], afrag[mi][1], afrag[mi][2], afrag[mi][3],
                        aBase + byte);
            }
            #pragma unroll
            for (int pr = 0; pr < 4; ++pr) {
                int row = warpN + pr * 16 + bRow;
                uint32_t byte = (uint32_t)(row * 128) +
                                ((uint32_t)((ks * 2 + bK8) * 16) ^ ((row & 7) * 16));
                uint32_t b0, b1, b2, b3;
                ldsm_x4(b0, b1, b2, b3, bBase + byte);
                #pragma unroll
                for (int mi = 0; mi < 2; ++mi) {
                    mma_fp16(acc[mi][pr * 2 + 0], afrag[mi], b0, b1);
                    mma_fp16(acc[mi][pr * 2 + 1], afrag[mi], b2, b3);
                }
            }
        }
        __syncthreads();
        ++buf; if (buf == NSTAGE) buf = 0;
    }

    // ---- masked RMW epilogue straight from accumulators ----
    const int mrow = lane >> 2;
    const int ncol = (lane & 3) * 2;
    #pragma unroll
    for (int mi = 0; mi < 2; ++mi) {
        #pragma unroll
        for (int ni = 0; ni < 8; ++ni) {
            const int m = bm + warpM + mi * 16 + mrow;
            const int n = bn + warpN + ni * 8 + ncol;
            size_t o = (size_t)m * N_DIM + n;
            if (g_mask[o])     Out[o]     += acc[mi][ni][0];
            if (g_mask[o + 1]) Out[o + 1] += acc[mi][ni][1];
            size_t o2 = o + (size_t)8 * N_DIM;
            if (g_mask[o2])     Out[o2]     += acc[mi][ni][2];
            if (g_mask[o2 + 1]) Out[o2 + 1] += acc[mi][ni][3];
        }
    }
}

// ---------------------------------------------------------------------------
extern "C" void kernel_launch(void* const* d_in, const int* in_sizes, int n_in,
                              void* d_out, int out_size)
{
    const float* x  = (const float*)d_in[0];   // [8192, 4096]
    const float* w  = (const float*)d_in[1];   // [4096, 4096]
    const float* bv = (const float*)d_in[2];   // [4096]
    float* out      = (float*)d_out;           // [8192, 4096]
    (void)in_sizes; (void)n_in; (void)out_size;

    cudaFuncSetAttribute(tail_mma_kernel,
                         cudaFuncAttributeMaxDynamicSharedMemorySize, SMEM_TOTAL_TAIL);

    __half *xh, *wh;
    cudaGetSymbolAddress((void**)&xh, g_Xh);
    cudaGetSymbolAddress((void**)&wh, g_Wh);

    // fp16 conversions (value path only)
    conv_half<<<(M_DIM * (KT / 4) + 255) / 256, 256>>>(x, xh, M_DIM);
    conv_half<<<(N_DIM * (KT / 4) + 255) / 256, 256>>>(w, wh, N_DIM);

    // Decision path (fp32 exact)
    dim3 headGrid(N_DIM / 64, M_DIM / 128);
    head_kernel<<<headGrid, 256>>>(x, w, bv, out);

    // Tail value path (single-pass fp16 HMMA)
    dim3 tailGrid(N_DIM / BN, M_DIM / BM);   // (32, 64)
    tail_mma_kernel<<<tailGrid, 256, SMEM_TOTAL_TAIL>>>(out);
}